// round 2
// baseline (speedup 1.0000x reference)
#include <cuda_runtime.h>

#define HID 64
#define GATES 192
#define BATCH 4096
#define TSTEPS 512
#define TILE_B 32
#define NCTA (BATCH / TILE_B)   // 128
#define NTHREADS 256

typedef unsigned long long ull;

// smem layout (float offsets)
#define OFF_W0   0              // Whh0^T k-major [64][192]
#define OFF_WA   12288          // Wih1^T [64][192]
#define OFF_WB   24576          // Whh1^T [64][192]
#define OFF_H0D  36864          // h0 dup state, 2 buffers x [64][64]
#define OFF_H1D  45056          // h1 dup state, 2 buffers
#define OFF_WIH0 53248          // Wih0 col-major [2][192]
#define OFF_BIH0 53632
#define OFF_BHH0 53824
#define OFF_BIH1 54016
#define OFF_BHH1 54208
#define OFF_WP   54400          // [128]
#define OFF_X0D  54528          // x col0 dup pairs [64]
#define OFF_X1D  54592          // x col1 dup pairs [64]
#define SMEM_FLOATS 54656
#define SMEM_BYTES (SMEM_FLOATS * 4)   // 218624 B

__device__ __forceinline__ ull ffma2(ull a, ull b, ull c) {
    ull d; asm("fma.rn.f32x2 %0, %1, %2, %3;" : "=l"(d) : "l"(a), "l"(b), "l"(c)); return d;
}
__device__ __forceinline__ ull fadd2(ull a, ull b) {
    ull d; asm("add.rn.f32x2 %0, %1, %2;" : "=l"(d) : "l"(a), "l"(b)); return d;
}
__device__ __forceinline__ ull dup2(float x) {
    ull d; asm("mov.b64 %0, {%1, %1};" : "=l"(d) : "f"(x)); return d;
}
__device__ __forceinline__ void unpk(ull v, float& lo, float& hi) {
    asm("mov.b64 {%0, %1}, %2;" : "=f"(lo), "=f"(hi) : "l"(v));
}
__device__ __forceinline__ float sigf(float v) {
    float e = __expf(-v); return __fdividef(1.0f, 1.0f + e);
}
__device__ __forceinline__ float tanhf_(float v) {
    float e = __expf(-2.0f * fabsf(v));
    float t = __fdividef(1.0f - e, 1.0f + e);
    return copysignf(t, v);
}

extern __shared__ float smem[];

__global__ void __launch_bounds__(NTHREADS, 1)
gru2_f32x2_kernel(const float* __restrict__ x,
                  const float* __restrict__ Wih0, const float* __restrict__ Whh0,
                  const float* __restrict__ bih0, const float* __restrict__ bhh0,
                  const float* __restrict__ Wih1, const float* __restrict__ Whh1,
                  const float* __restrict__ bih1, const float* __restrict__ bhh1,
                  const float* __restrict__ Wp,   const float* __restrict__ bp,
                  float* __restrict__ out)
{
    const int tid = threadIdx.x;
    const int b0  = blockIdx.x * TILE_B;

    float* w0s  = smem + OFF_W0;
    float* was  = smem + OFF_WA;
    float* wbs  = smem + OFF_WB;
    float* h0bs = smem + OFF_H0D;
    float* h1bs = smem + OFF_H1D;
    float* x0d  = smem + OFF_X0D;
    float* x1d  = smem + OFF_X1D;

    // ---- prologue: coalesced weight reads, smem transpose to k-major
    for (int d = tid; d < HID * GATES; d += NTHREADS) {
        int g = d >> 6, k = d & 63;      // source [192][64] row-major
        int o = k * GATES + g;
        w0s[o] = Whh0[d];
        was[o] = Wih1[d];
        wbs[o] = Whh1[d];
    }
    for (int g = tid; g < GATES; g += NTHREADS) {
        smem[OFF_WIH0 + g]         = Wih0[2 * g];
        smem[OFF_WIH0 + GATES + g] = Wih0[2 * g + 1];
        smem[OFF_BIH0 + g] = bih0[g];
        smem[OFF_BHH0 + g] = bhh0[g];
        smem[OFF_BIH1 + g] = bih1[g];
        smem[OFF_BHH1 + g] = bhh1[g];
    }
    if (tid < 2 * HID) smem[OFF_WP + tid] = Wp[tid];
    for (int d = tid; d < 8192; d += NTHREADS) { h0bs[d] = 0.0f; h1bs[d] = 0.0f; }
    if (tid < TILE_B) {
        float2 xv = *(const float2*)(x + (size_t)(b0 + tid) * 2);
        *(ull*)(x0d + 2 * tid) = dup2(xv.x);
        *(ull*)(x1d + 2 * tid) = dup2(xv.y);
    }
    __syncthreads();

    // thread tiling: jg = gate-pair index (j0 = jg*2 in each of 3 blocks),
    // bg = batch group of 4. Within a warp: bg = lane&7 (8 groups), 4 jg values.
    const int jg = tid >> 3;            // 0..31
    const int bg = tid & 7;             // 0..7
    const int j0 = jg * 2;
    const int bb = bg * 4;

    // loop-invariant weight/bias pairs in registers
    ull xw0[3], xw1[3];
    #pragma unroll
    for (int blk = 0; blk < 3; ++blk) {
        xw0[blk] = *(const ull*)(smem + OFF_WIH0 + blk * 64 + j0);
        xw1[blk] = *(const ull*)(smem + OFF_WIH0 + GATES + blk * 64 + j0);
    }
    const float* bi0 = smem + OFF_BIH0;
    const float* bh0 = smem + OFF_BHH0;
    const float* bi1 = smem + OFF_BIH1;
    const float* bh1 = smem + OFF_BHH1;
    ull bc0_r = fadd2(*(const ull*)(bi0 + j0),      *(const ull*)(bh0 + j0));
    ull bc0_z = fadd2(*(const ull*)(bi0 + 64 + j0), *(const ull*)(bh0 + 64 + j0));
    ull xb2   = *(const ull*)(bi0 + 128 + j0);
    ull bh0n  = *(const ull*)(bh0 + 128 + j0);
    ull bc1_r = fadd2(*(const ull*)(bi1 + j0),      *(const ull*)(bh1 + j0));
    ull bc1_z = fadd2(*(const ull*)(bi1 + 64 + j0), *(const ull*)(bh1 + 64 + j0));
    ull bi1n  = *(const ull*)(bi1 + 128 + j0);
    ull bh1n  = *(const ull*)(bh1 + 128 + j0);

    // conflict-free dup-layout position of (hidden j, batch b) within a k-row:
    // pos = j*64 + pb, pb = (b&2)<<4 | (b>>2)<<2 | (b&1)<<1
    const int pb0 = ((bb & 2) << 4) + (bg << 2);   // base for i=0 (b=bb, bb even)

    for (int t = 0; t < TSTEPS; ++t) {
        const int p = (t & 1) << 12;
        float* h0r = h0bs + p;
        float* h0w = h0bs + (p ^ 4096);
        float* h1r = h1bs + p;
        float* h1w = h1bs + (p ^ 4096);

        // ================= phase 1: GEMM1 (h0 @ Whh0^T) + gates L0 =================
        ull a0[4], a1[4], a2[4];
        #pragma unroll
        for (int i = 0; i < 4; ++i) { a0[i] = bc0_r; a1[i] = bc0_z; a2[i] = bh0n; }

        #pragma unroll 4
        for (int k = 0; k < HID; ++k) {
            const float* hr = h0r + k * 64;
            ulonglong2 p0 = *(const ulonglong2*)(hr + (bg << 2));
            ulonglong2 p1 = *(const ulonglong2*)(hr + 32 + (bg << 2));
            const float* wr = w0s + k * GATES + j0;
            ull w0 = *(const ull*)(wr);
            ull w1 = *(const ull*)(wr + 64);
            ull w2 = *(const ull*)(wr + 128);
            a0[0] = ffma2(w0, p0.x, a0[0]); a0[1] = ffma2(w0, p0.y, a0[1]);
            a0[2] = ffma2(w0, p1.x, a0[2]); a0[3] = ffma2(w0, p1.y, a0[3]);
            a1[0] = ffma2(w1, p0.x, a1[0]); a1[1] = ffma2(w1, p0.y, a1[1]);
            a1[2] = ffma2(w1, p1.x, a1[2]); a1[3] = ffma2(w1, p1.y, a1[3]);
            a2[0] = ffma2(w2, p0.x, a2[0]); a2[1] = ffma2(w2, p0.y, a2[1]);
            a2[2] = ffma2(w2, p1.x, a2[2]); a2[3] = ffma2(w2, p1.y, a2[3]);
        }

        #pragma unroll
        for (int i = 0; i < 4; ++i) {
            int b  = bb + i;
            int pb = pb0 + ((i & 2) << 4) + ((i & 1) << 1);
            ull x0p = *(const ull*)(x0d + 2 * b);
            ull x1p = *(const ull*)(x1d + 2 * b);
            ull pr = ffma2(x1p, xw1[0], ffma2(x0p, xw0[0], a0[i]));
            ull pz = ffma2(x1p, xw1[1], ffma2(x0p, xw0[1], a1[i]));
            ull xn = ffma2(x1p, xw1[2], ffma2(x0p, xw0[2], xb2));
            float rl, rh, zl, zh, xnl, xnh, hnl, hnh;
            unpk(pr, rl, rh); unpk(pz, zl, zh);
            unpk(xn, xnl, xnh); unpk(a2[i], hnl, hnh);
            rl = sigf(rl); rh = sigf(rh);
            zl = sigf(zl); zh = sigf(zh);
            float nl = tanhf_(fmaf(rl, hnl, xnl));
            float nh = tanhf_(fmaf(rh, hnh, xnh));
            float hpl = h0r[j0 * 64 + pb];
            float hph = h0r[(j0 + 1) * 64 + pb];
            float ol = fmaf(zl, hpl - nl, nl);
            float oh = fmaf(zh, hph - nh, nh);
            *(ull*)(h0w + j0 * 64 + pb)       = dup2(ol);
            *(ull*)(h0w + (j0 + 1) * 64 + pb) = dup2(oh);
        }
        __syncthreads();

        // ================= phase 2: GEMM2 (h0new@Wih1 + h1@Whh1) + gates L1 =========
        float2 xv = make_float2(0.0f, 0.0f);
        if (tid < TILE_B && t + 1 < TSTEPS)
            xv = *(const float2*)(x + ((size_t)(t + 1) * BATCH + b0 + tid) * 2);

        ull c0[4], c1[4], cA[4], cB[4];
        #pragma unroll
        for (int i = 0; i < 4; ++i) { c0[i] = bc1_r; c1[i] = bc1_z; cA[i] = bi1n; cB[i] = bh1n; }

        #pragma unroll 2
        for (int k = 0; k < HID; ++k) {
            const float* ar = h0w + k * 64;
            const float* br = h1r + k * 64;
            ulonglong2 pa0 = *(const ulonglong2*)(ar + (bg << 2));
            ulonglong2 pa1 = *(const ulonglong2*)(ar + 32 + (bg << 2));
            ulonglong2 qb0 = *(const ulonglong2*)(br + (bg << 2));
            ulonglong2 qb1 = *(const ulonglong2*)(br + 32 + (bg << 2));
            const float* wa = was + k * GATES + j0;
            const float* wb = wbs + k * GATES + j0;
            ull wa0 = *(const ull*)(wa);
            ull wa1 = *(const ull*)(wa + 64);
            ull wa2 = *(const ull*)(wa + 128);
            ull wb0 = *(const ull*)(wb);
            ull wb1 = *(const ull*)(wb + 64);
            ull wb2 = *(const ull*)(wb + 128);
            c0[0] = ffma2(wa0, pa0.x, c0[0]); c0[0] = ffma2(wb0, qb0.x, c0[0]);
            c0[1] = ffma2(wa0, pa0.y, c0[1]); c0[1] = ffma2(wb0, qb0.y, c0[1]);
            c0[2] = ffma2(wa0, pa1.x, c0[2]); c0[2] = ffma2(wb0, qb1.x, c0[2]);
            c0[3] = ffma2(wa0, pa1.y, c0[3]); c0[3] = ffma2(wb0, qb1.y, c0[3]);
            c1[0] = ffma2(wa1, pa0.x, c1[0]); c1[0] = ffma2(wb1, qb0.x, c1[0]);
            c1[1] = ffma2(wa1, pa0.y, c1[1]); c1[1] = ffma2(wb1, qb0.y, c1[1]);
            c1[2] = ffma2(wa1, pa1.x, c1[2]); c1[2] = ffma2(wb1, qb1.x, c1[2]);
            c1[3] = ffma2(wa1, pa1.y, c1[3]); c1[3] = ffma2(wb1, qb1.y, c1[3]);
            cA[0] = ffma2(wa2, pa0.x, cA[0]); cB[0] = ffma2(wb2, qb0.x, cB[0]);
            cA[1] = ffma2(wa2, pa0.y, cA[1]); cB[1] = ffma2(wb2, qb0.y, cB[1]);
            cA[2] = ffma2(wa2, pa1.x, cA[2]); cB[2] = ffma2(wb2, qb1.x, cB[2]);
            cA[3] = ffma2(wa2, pa1.y, cA[3]); cB[3] = ffma2(wb2, qb1.y, cB[3]);
        }

        // stage x for step t+1 (LDG issued before the k-loop, long since landed)
        if (tid < TILE_B) {
            *(ull*)(x0d + 2 * tid) = dup2(xv.x);
            *(ull*)(x1d + 2 * tid) = dup2(xv.y);
        }

        #pragma unroll
        for (int i = 0; i < 4; ++i) {
            int pb = pb0 + ((i & 2) << 4) + ((i & 1) << 1);
            float rl, rh, zl, zh, xnl, xnh, hnl, hnh;
            unpk(c0[i], rl, rh); unpk(c1[i], zl, zh);
            unpk(cA[i], xnl, xnh); unpk(cB[i], hnl, hnh);
            rl = sigf(rl); rh = sigf(rh);
            zl = sigf(zl); zh = sigf(zh);
            float nl = tanhf_(fmaf(rl, hnl, xnl));
            float nh = tanhf_(fmaf(rh, hnh, xnh));
            float hpl = h1r[j0 * 64 + pb];
            float hph = h1r[(j0 + 1) * 64 + pb];
            float ol = fmaf(zl, hpl - nl, nl);
            float oh = fmaf(zh, hph - nh, nh);
            *(ull*)(h1w + j0 * 64 + pb)       = dup2(ol);
            *(ull*)(h1w + (j0 + 1) * 64 + pb) = dup2(oh);
        }
        __syncthreads();
    }

    // ---- final projection: final states live in buffer 0 (TSTEPS even)
    if (tid < TILE_B) {
        int b  = tid;
        int pb = ((b & 2) << 4) + ((b >> 2) << 2) + ((b & 1) << 1);
        const float* wps = smem + OFF_WP;
        float s = bp[0];
        #pragma unroll 8
        for (int k = 0; k < HID; ++k) s = fmaf(h0bs[k * 64 + pb], wps[k], s);
        #pragma unroll 8
        for (int k = 0; k < HID; ++k) s = fmaf(h1bs[k * 64 + pb], wps[HID + k], s);
        out[b0 + tid] = s;
    }
}

extern "C" void kernel_launch(void* const* d_in, const int* in_sizes, int n_in,
                              void* d_out, int out_size) {
    const float* x    = (const float*)d_in[0];
    const float* Wih0 = (const float*)d_in[1];
    const float* Whh0 = (const float*)d_in[2];
    const float* bih0 = (const float*)d_in[3];
    const float* bhh0 = (const float*)d_in[4];
    const float* Wih1 = (const float*)d_in[5];
    const float* Whh1 = (const float*)d_in[6];
    const float* bih1 = (const float*)d_in[7];
    const float* bhh1 = (const float*)d_in[8];
    const float* Wp   = (const float*)d_in[9];
    const float* bp   = (const float*)d_in[10];
    float* out = (float*)d_out;

    cudaFuncSetAttribute(gru2_f32x2_kernel,
                         cudaFuncAttributeMaxDynamicSharedMemorySize, SMEM_BYTES);
    gru2_f32x2_kernel<<<NCTA, NTHREADS, SMEM_BYTES>>>(
        x, Wih0, Whh0, bih0, bhh0, Wih1, Whh1, bih1, bhh1, Wp, bp, out);
}

// round 3
// speedup vs baseline: 1.6482x; 1.6482x over previous
#include <cuda_runtime.h>

#define HID 64
#define GATES 192
#define BATCH 4096
#define TSTEPS 512
#define TILE_B 32
#define NCTA (BATCH / TILE_B)   // 128
#define NTHREADS 256

typedef unsigned long long ull;

// smem layout (float offsets)
#define OFF_W0   0              // Whh0^T k-major [64][192]
#define OFF_WA   12288          // Wih1^T [64][192]
#define OFF_WB   24576          // Whh1^T [64][192]
#define OFF_H0D  36864          // h0 dup state, 2 buffers x [64][64]
#define OFF_H1D  45056          // h1 dup state, 2 buffers
#define OFF_WIH0 53248          // Wih0 col-major [2][192]
#define OFF_BIH0 53632
#define OFF_BHH0 53824
#define OFF_BIH1 54016
#define OFF_BHH1 54208
#define OFF_WP   54400          // [128]
#define OFF_X0D  54528          // x col0 dup pairs [64]
#define OFF_X1D  54592          // x col1 dup pairs [64]
#define SMEM_FLOATS 54656
#define SMEM_BYTES (SMEM_FLOATS * 4)   // 218624 B

__device__ __forceinline__ ull ffma2(ull a, ull b, ull c) {
    ull d; asm("fma.rn.f32x2 %0, %1, %2, %3;" : "=l"(d) : "l"(a), "l"(b), "l"(c)); return d;
}
__device__ __forceinline__ ull fadd2(ull a, ull b) {
    ull d; asm("add.rn.f32x2 %0, %1, %2;" : "=l"(d) : "l"(a), "l"(b)); return d;
}
__device__ __forceinline__ ull dup2(float x) {
    ull d; asm("mov.b64 %0, {%1, %1};" : "=l"(d) : "f"(x)); return d;
}
__device__ __forceinline__ void unpk(ull v, float& lo, float& hi) {
    asm("mov.b64 {%0, %1}, %2;" : "=f"(lo), "=f"(hi) : "l"(v));
}
__device__ __forceinline__ float sigf(float v) {
    float e = __expf(-v); return __fdividef(1.0f, 1.0f + e);
}
__device__ __forceinline__ float tanhf_(float v) {
    float e = __expf(-2.0f * fabsf(v));
    float t = __fdividef(1.0f - e, 1.0f + e);
    return copysignf(t, v);
}

extern __shared__ float smem[];

__global__ void __launch_bounds__(NTHREADS, 1)
gru2_f32x2_kernel(const float* __restrict__ x,
                  const float* __restrict__ Wih0, const float* __restrict__ Whh0,
                  const float* __restrict__ bih0, const float* __restrict__ bhh0,
                  const float* __restrict__ Wih1, const float* __restrict__ Whh1,
                  const float* __restrict__ bih1, const float* __restrict__ bhh1,
                  const float* __restrict__ Wp,   const float* __restrict__ bp,
                  float* __restrict__ out)
{
    const int tid = threadIdx.x;
    const int b0  = blockIdx.x * TILE_B;

    float* w0s  = smem + OFF_W0;
    float* was  = smem + OFF_WA;
    float* wbs  = smem + OFF_WB;
    float* h0bs = smem + OFF_H0D;
    float* h1bs = smem + OFF_H1D;
    float* x0d  = smem + OFF_X0D;
    float* x1d  = smem + OFF_X1D;

    // ---- prologue: coalesced weight reads, smem transpose to k-major
    for (int d = tid; d < HID * GATES; d += NTHREADS) {
        int g = d >> 6, k = d & 63;      // source [192][64] row-major
        int o = k * GATES + g;
        w0s[o] = Whh0[d];
        was[o] = Wih1[d];
        wbs[o] = Whh1[d];
    }
    for (int g = tid; g < GATES; g += NTHREADS) {
        smem[OFF_WIH0 + g]         = Wih0[2 * g];
        smem[OFF_WIH0 + GATES + g] = Wih0[2 * g + 1];
        smem[OFF_BIH0 + g] = bih0[g];
        smem[OFF_BHH0 + g] = bhh0[g];
        smem[OFF_BIH1 + g] = bih1[g];
        smem[OFF_BHH1 + g] = bhh1[g];
    }
    if (tid < 2 * HID) smem[OFF_WP + tid] = Wp[tid];
    for (int d = tid; d < 8192; d += NTHREADS) { h0bs[d] = 0.0f; h1bs[d] = 0.0f; }
    if (tid < TILE_B) {
        float2 xv = *(const float2*)(x + (size_t)(b0 + tid) * 2);
        *(ull*)(x0d + 2 * tid) = dup2(xv.x);
        *(ull*)(x1d + 2 * tid) = dup2(xv.y);
    }
    __syncthreads();

    // thread tiling: jg = gate-pair index (j0 = jg*2 in each of 3 blocks),
    // bg = batch group of 4. Within a warp: bg = lane&7 (8 groups), 4 jg values.
    const int jg = tid >> 3;            // 0..31
    const int bg = tid & 7;             // 0..7
    const int j0 = jg * 2;
    const int bb = bg * 4;

    // loop-invariant weight/bias pairs in registers
    ull xw0[3], xw1[3];
    #pragma unroll
    for (int blk = 0; blk < 3; ++blk) {
        xw0[blk] = *(const ull*)(smem + OFF_WIH0 + blk * 64 + j0);
        xw1[blk] = *(const ull*)(smem + OFF_WIH0 + GATES + blk * 64 + j0);
    }
    const float* bi0 = smem + OFF_BIH0;
    const float* bh0 = smem + OFF_BHH0;
    const float* bi1 = smem + OFF_BIH1;
    const float* bh1 = smem + OFF_BHH1;
    ull bc0_r = fadd2(*(const ull*)(bi0 + j0),      *(const ull*)(bh0 + j0));
    ull bc0_z = fadd2(*(const ull*)(bi0 + 64 + j0), *(const ull*)(bh0 + 64 + j0));
    ull xb2   = *(const ull*)(bi0 + 128 + j0);
    ull bh0n  = *(const ull*)(bh0 + 128 + j0);
    ull bc1_r = fadd2(*(const ull*)(bi1 + j0),      *(const ull*)(bh1 + j0));
    ull bc1_z = fadd2(*(const ull*)(bi1 + 64 + j0), *(const ull*)(bh1 + 64 + j0));
    ull bi1n  = *(const ull*)(bi1 + 128 + j0);
    ull bh1n  = *(const ull*)(bh1 + 128 + j0);

    // conflict-free dup-layout position of (hidden j, batch b) within a k-row:
    // pos = j*64 + pb, pb = (b&2)<<4 | (b>>2)<<2 | (b&1)<<1
    const int pb0 = ((bb & 2) << 4) + (bg << 2);   // base for i=0 (b=bb, bb even)

    for (int t = 0; t < TSTEPS; ++t) {
        const int p = (t & 1) << 12;
        float* h0r = h0bs + p;
        float* h0w = h0bs + (p ^ 4096);
        float* h1r = h1bs + p;
        float* h1w = h1bs + (p ^ 4096);

        // ================= phase 1: GEMM1 (h0 @ Whh0^T) + gates L0 =================
        ull a0[4], a1[4], a2[4];
        #pragma unroll
        for (int i = 0; i < 4; ++i) { a0[i] = bc0_r; a1[i] = bc0_z; a2[i] = bh0n; }

        #pragma unroll 4
        for (int k = 0; k < HID; ++k) {
            const float* hr = h0r + k * 64;
            ulonglong2 p0 = *(const ulonglong2*)(hr + (bg << 2));
            ulonglong2 p1 = *(const ulonglong2*)(hr + 32 + (bg << 2));
            const float* wr = w0s + k * GATES + j0;
            ull w0 = *(const ull*)(wr);
            ull w1 = *(const ull*)(wr + 64);
            ull w2 = *(const ull*)(wr + 128);
            a0[0] = ffma2(w0, p0.x, a0[0]); a0[1] = ffma2(w0, p0.y, a0[1]);
            a0[2] = ffma2(w0, p1.x, a0[2]); a0[3] = ffma2(w0, p1.y, a0[3]);
            a1[0] = ffma2(w1, p0.x, a1[0]); a1[1] = ffma2(w1, p0.y, a1[1]);
            a1[2] = ffma2(w1, p1.x, a1[2]); a1[3] = ffma2(w1, p1.y, a1[3]);
            a2[0] = ffma2(w2, p0.x, a2[0]); a2[1] = ffma2(w2, p0.y, a2[1]);
            a2[2] = ffma2(w2, p1.x, a2[2]); a2[3] = ffma2(w2, p1.y, a2[3]);
        }

        #pragma unroll
        for (int i = 0; i < 4; ++i) {
            int b  = bb + i;
            int pb = pb0 + ((i & 2) << 4) + ((i & 1) << 1);
            ull x0p = *(const ull*)(x0d + 2 * b);
            ull x1p = *(const ull*)(x1d + 2 * b);
            ull pr = ffma2(x1p, xw1[0], ffma2(x0p, xw0[0], a0[i]));
            ull pz = ffma2(x1p, xw1[1], ffma2(x0p, xw0[1], a1[i]));
            ull xn = ffma2(x1p, xw1[2], ffma2(x0p, xw0[2], xb2));
            float rl, rh, zl, zh, xnl, xnh, hnl, hnh;
            unpk(pr, rl, rh); unpk(pz, zl, zh);
            unpk(xn, xnl, xnh); unpk(a2[i], hnl, hnh);
            rl = sigf(rl); rh = sigf(rh);
            zl = sigf(zl); zh = sigf(zh);
            float nl = tanhf_(fmaf(rl, hnl, xnl));
            float nh = tanhf_(fmaf(rh, hnh, xnh));
            float hpl = h0r[j0 * 64 + pb];
            float hph = h0r[(j0 + 1) * 64 + pb];
            float ol = fmaf(zl, hpl - nl, nl);
            float oh = fmaf(zh, hph - nh, nh);
            *(ull*)(h0w + j0 * 64 + pb)       = dup2(ol);
            *(ull*)(h0w + (j0 + 1) * 64 + pb) = dup2(oh);
        }
        __syncthreads();

        // ================= phase 2: GEMM2 (h0new@Wih1 + h1@Whh1) + gates L1 =========
        float2 xv = make_float2(0.0f, 0.0f);
        if (tid < TILE_B && t + 1 < TSTEPS)
            xv = *(const float2*)(x + ((size_t)(t + 1) * BATCH + b0 + tid) * 2);

        ull c0[4], c1[4], cA[4], cB[4];
        #pragma unroll
        for (int i = 0; i < 4; ++i) { c0[i] = bc1_r; c1[i] = bc1_z; cA[i] = bi1n; cB[i] = bh1n; }

        #pragma unroll 2
        for (int k = 0; k < HID; ++k) {
            const float* ar = h0w + k * 64;
            const float* br = h1r + k * 64;
            ulonglong2 pa0 = *(const ulonglong2*)(ar + (bg << 2));
            ulonglong2 pa1 = *(const ulonglong2*)(ar + 32 + (bg << 2));
            ulonglong2 qb0 = *(const ulonglong2*)(br + (bg << 2));
            ulonglong2 qb1 = *(const ulonglong2*)(br + 32 + (bg << 2));
            const float* wa = was + k * GATES + j0;
            const float* wb = wbs + k * GATES + j0;
            ull wa0 = *(const ull*)(wa);
            ull wa1 = *(const ull*)(wa + 64);
            ull wa2 = *(const ull*)(wa + 128);
            ull wb0 = *(const ull*)(wb);
            ull wb1 = *(const ull*)(wb + 64);
            ull wb2 = *(const ull*)(wb + 128);
            c0[0] = ffma2(wa0, pa0.x, c0[0]); c0[0] = ffma2(wb0, qb0.x, c0[0]);
            c0[1] = ffma2(wa0, pa0.y, c0[1]); c0[1] = ffma2(wb0, qb0.y, c0[1]);
            c0[2] = ffma2(wa0, pa1.x, c0[2]); c0[2] = ffma2(wb0, qb1.x, c0[2]);
            c0[3] = ffma2(wa0, pa1.y, c0[3]); c0[3] = ffma2(wb0, qb1.y, c0[3]);
            c1[0] = ffma2(wa1, pa0.x, c1[0]); c1[0] = ffma2(wb1, qb0.x, c1[0]);
            c1[1] = ffma2(wa1, pa0.y, c1[1]); c1[1] = ffma2(wb1, qb0.y, c1[1]);
            c1[2] = ffma2(wa1, pa1.x, c1[2]); c1[2] = ffma2(wb1, qb1.x, c1[2]);
            c1[3] = ffma2(wa1, pa1.y, c1[3]); c1[3] = ffma2(wb1, qb1.y, c1[3]);
            cA[0] = ffma2(wa2, pa0.x, cA[0]); cB[0] = ffma2(wb2, qb0.x, cB[0]);
            cA[1] = ffma2(wa2, pa0.y, cA[1]); cB[1] = ffma2(wb2, qb0.y, cB[1]);
            cA[2] = ffma2(wa2, pa1.x, cA[2]); cB[2] = ffma2(wb2, qb1.x, cB[2]);
            cA[3] = ffma2(wa2, pa1.y, cA[3]); cB[3] = ffma2(wb2, qb1.y, cB[3]);
        }

        // stage x for step t+1 (LDG issued before the k-loop, long since landed)
        if (tid < TILE_B) {
            *(ull*)(x0d + 2 * tid) = dup2(xv.x);
            *(ull*)(x1d + 2 * tid) = dup2(xv.y);
        }

        #pragma unroll
        for (int i = 0; i < 4; ++i) {
            int pb = pb0 + ((i & 2) << 4) + ((i & 1) << 1);
            float rl, rh, zl, zh, xnl, xnh, hnl, hnh;
            unpk(c0[i], rl, rh); unpk(c1[i], zl, zh);
            unpk(cA[i], xnl, xnh); unpk(cB[i], hnl, hnh);
            rl = sigf(rl); rh = sigf(rh);
            zl = sigf(zl); zh = sigf(zh);
            float nl = tanhf_(fmaf(rl, hnl, xnl));
            float nh = tanhf_(fmaf(rh, hnh, xnh));
            float hpl = h1r[j0 * 64 + pb];
            float hph = h1r[(j0 + 1) * 64 + pb];
            float ol = fmaf(zl, hpl - nl, nl);
            float oh = fmaf(zh, hph - nh, nh);
            *(ull*)(h1w + j0 * 64 + pb)       = dup2(ol);
            *(ull*)(h1w + (j0 + 1) * 64 + pb) = dup2(oh);
        }
        __syncthreads();
    }

    // ---- final projection: final states live in buffer 0 (TSTEPS even)
    if (tid < TILE_B) {
        int b  = tid;
        int pb = ((b & 2) << 4) + ((b >> 2) << 2) + ((b & 1) << 1);
        const float* wps = smem + OFF_WP;
        float s = bp[0];
        #pragma unroll 8
        for (int k = 0; k < HID; ++k) s = fmaf(h0bs[k * 64 + pb], wps[k], s);
        #pragma unroll 8
        for (int k = 0; k < HID; ++k) s = fmaf(h1bs[k * 64 + pb], wps[HID + k], s);
        out[b0 + tid] = s;
    }
}

extern "C" void kernel_launch(void* const* d_in, const int* in_sizes, int n_in,
                              void* d_out, int out_size) {
    const float* x    = (const float*)d_in[0];
    const float* Wih0 = (const float*)d_in[1];
    const float* Whh0 = (const float*)d_in[2];
    const float* bih0 = (const float*)d_in[3];
    const float* bhh0 = (const float*)d_in[4];
    const float* Wih1 = (const float*)d_in[5];
    const float* Whh1 = (const float*)d_in[6];
    const float* bih1 = (const float*)d_in[7];
    const float* bhh1 = (const float*)d_in[8];
    const float* Wp   = (const float*)d_in[9];
    const float* bp   = (const float*)d_in[10];
    float* out = (float*)d_out;

    cudaFuncSetAttribute(gru2_f32x2_kernel,
                         cudaFuncAttributeMaxDynamicSharedMemorySize, SMEM_BYTES);
    gru2_f32x2_kernel<<<NCTA, NTHREADS, SMEM_BYTES>>>(
        x, Wih0, Whh0, bih0, bhh0, Wih1, Whh1, bih1, bhh1, Wp, bp, out);
}

// round 4
// speedup vs baseline: 1.8938x; 1.1490x over previous
#include <cuda_runtime.h>

#define HID 64
#define GATES 192
#define BATCH 4096
#define TSTEPS 512
#define TILE_B 32
#define NCTA 128
#define NTHREADS 256

typedef unsigned long long ull;

// smem layout (float offsets)
#define OFF_W0   0        // Whh0^T k-major [64][192], r/z rows pre-scaled 0.5
#define OFF_WA   12288    // Wih1^T
#define OFF_WB   24576    // Whh1^T
#define OFF_H0D  36864    // h0 dup state, 2 buffers x [64][64]
#define OFF_H1D  45056
#define OFF_WIH0 53248    // Wih0 col-major [2][192], r/z scaled 0.5
#define OFF_MB0  53632    // merged 0.5*(bih0+bhh0) r/z [128]
#define OFF_B0NX 53760    // bih0 n [64]
#define OFF_B0NH 53824    // bhh0 n [64]
#define OFF_MB1  53888    // merged 0.5*(bih1+bhh1) r/z [128]
#define OFF_B1NA 54016    // bih1 n [64]
#define OFF_B1NB 54080    // bhh1 n [64]
#define OFF_WP   54144    // [128]
#define OFF_X0D  54272    // x col0 dup pairs [64]
#define OFF_X1D  54336
#define SMEM_FLOATS 54400
#define SMEM_BYTES (SMEM_FLOATS * 4)   // 217600 B

__device__ __forceinline__ ull ffma2(ull a, ull b, ull c) {
    ull d; asm("fma.rn.f32x2 %0, %1, %2, %3;" : "=l"(d) : "l"(a), "l"(b), "l"(c)); return d;
}
__device__ __forceinline__ ull dup2(float x) {
    ull d; asm("mov.b64 %0, {%1, %1};" : "=l"(d) : "f"(x)); return d;
}
__device__ __forceinline__ void unpk(ull v, float& lo, float& hi) {
    asm("mov.b64 {%0, %1}, %2;" : "=f"(lo), "=f"(hi) : "l"(v));
}
__device__ __forceinline__ float tanhx(float v) {
    float y; asm("tanh.approx.f32 %0, %1;" : "=f"(y) : "f"(v)); return y;
}

extern __shared__ float smem[];

__global__ void __launch_bounds__(NTHREADS, 1)
gru2_r4_kernel(const float* __restrict__ x,
               const float* __restrict__ Wih0, const float* __restrict__ Whh0,
               const float* __restrict__ bih0, const float* __restrict__ bhh0,
               const float* __restrict__ Wih1, const float* __restrict__ Whh1,
               const float* __restrict__ bih1, const float* __restrict__ bhh1,
               const float* __restrict__ Wp,   const float* __restrict__ bp,
               float* __restrict__ out)
{
    const int tid = threadIdx.x;
    const int b0  = blockIdx.x * TILE_B;

    float* w0s   = smem + OFF_W0;
    float* was   = smem + OFF_WA;
    float* wbs   = smem + OFF_WB;
    float* h0bs  = smem + OFF_H0D;
    float* h1bs  = smem + OFF_H1D;
    float* wih0s = smem + OFF_WIH0;
    float* x0d   = smem + OFF_X0D;
    float* x1d   = smem + OFF_X1D;

    // ---- prologue: transpose weights to k-major, pre-scale r/z by 0.5 ----
    for (int d = tid; d < HID * GATES; d += NTHREADS) {
        int g = d >> 6, k = d & 63;            // source [192][64] row-major
        float s = (g < 128) ? 0.5f : 1.0f;
        int o = k * GATES + g;
        w0s[o] = Whh0[d] * s;
        was[o] = Wih1[d] * s;
        wbs[o] = Whh1[d] * s;
    }
    for (int g = tid; g < GATES; g += NTHREADS) {
        float s = (g < 128) ? 0.5f : 1.0f;
        wih0s[g]         = Wih0[2 * g]     * s;
        wih0s[GATES + g] = Wih0[2 * g + 1] * s;
    }
    if (tid < 128) {
        smem[OFF_MB0 + tid] = 0.5f * (bih0[tid] + bhh0[tid]);
        smem[OFF_MB1 + tid] = 0.5f * (bih1[tid] + bhh1[tid]);
        smem[OFF_WP + tid]  = Wp[tid];
    }
    if (tid < 64) {
        smem[OFF_B0NX + tid] = bih0[128 + tid];
        smem[OFF_B0NH + tid] = bhh0[128 + tid];
        smem[OFF_B1NA + tid] = bih1[128 + tid];
        smem[OFF_B1NB + tid] = bhh1[128 + tid];
    }
    for (int d = tid; d < 16384; d += NTHREADS) h0bs[d] = 0.0f;   // zeroes h0 both + h1 both
    if (tid < TILE_B) {
        float2 xv = *(const float2*)(x + (size_t)(b0 + tid) * 2);
        *(ull*)(x0d + 2 * tid) = dup2(xv.x);
        *(ull*)(x1d + 2 * tid) = dup2(xv.y);
    }
    __syncthreads();

    // tiling: gg = gate group (4 gates per block), bg = batch pair
    // lane = bg (low 4 bits) -> weight LDS broadcast across 16 lanes
    const int gg = tid >> 4;        // 0..15
    const int bg = tid & 15;        // 0..15
    const int j0 = gg * 4;
    const int hoff = bg * 4;        // dup-pair offset within a 64-float k-row

    float hp0[8], hp1[8];           // prev h for (jj, q): idx = jj*2+q
    #pragma unroll
    for (int i = 0; i < 8; ++i) { hp0[i] = 0.0f; hp1[i] = 0.0f; }

    for (int t = 0; t < TSTEPS; ++t) {
        const int p = (t & 1) << 12;
        float* h0r = h0bs + p;
        float* h0w = h0bs + (p ^ 4096);
        float* h1r = h1bs + p;
        float* h1w = h1bs + (p ^ 4096);

        // ============ phase 1: GEMM1 (h0 @ Whh0^T) + gates L0 ============
        ulonglong2 s_r = *(const ulonglong2*)(smem + OFF_MB0 + j0);
        ulonglong2 s_z = *(const ulonglong2*)(smem + OFF_MB0 + 64 + j0);
        ulonglong2 s_n = *(const ulonglong2*)(smem + OFF_B0NH + j0);
        ull ar[4], az[4], an[4];
        ar[0] = s_r.x; ar[1] = s_r.x; ar[2] = s_r.y; ar[3] = s_r.y;
        az[0] = s_z.x; az[1] = s_z.x; az[2] = s_z.y; az[3] = s_z.y;
        an[0] = s_n.x; an[1] = s_n.x; an[2] = s_n.y; an[3] = s_n.y;

        #pragma unroll 8
        for (int k = 0; k < HID; ++k) {
            ulonglong2 h   = *(const ulonglong2*)(h0r + k * 64 + hoff);
            const float* w = w0s + k * GATES + j0;
            ulonglong2 w_r = *(const ulonglong2*)(w);
            ulonglong2 w_z = *(const ulonglong2*)(w + 64);
            ulonglong2 w_n = *(const ulonglong2*)(w + 128);
            ar[0] = ffma2(w_r.x, h.x, ar[0]); ar[1] = ffma2(w_r.x, h.y, ar[1]);
            ar[2] = ffma2(w_r.y, h.x, ar[2]); ar[3] = ffma2(w_r.y, h.y, ar[3]);
            az[0] = ffma2(w_z.x, h.x, az[0]); az[1] = ffma2(w_z.x, h.y, az[1]);
            az[2] = ffma2(w_z.y, h.x, az[2]); az[3] = ffma2(w_z.y, h.y, az[3]);
            an[0] = ffma2(w_n.x, h.x, an[0]); an[1] = ffma2(w_n.x, h.y, an[1]);
            an[2] = ffma2(w_n.y, h.x, an[2]); an[3] = ffma2(w_n.y, h.y, an[3]);
        }

        // epilogue L0: add x-side gates, nonlinearity, write dup state
        {
            ulonglong2 xw0r = *(const ulonglong2*)(wih0s + j0);
            ulonglong2 xw0z = *(const ulonglong2*)(wih0s + 64 + j0);
            ulonglong2 xw0n = *(const ulonglong2*)(wih0s + 128 + j0);
            ulonglong2 xw1r = *(const ulonglong2*)(wih0s + GATES + j0);
            ulonglong2 xw1z = *(const ulonglong2*)(wih0s + GATES + 64 + j0);
            ulonglong2 xw1n = *(const ulonglong2*)(wih0s + GATES + 128 + j0);
            ulonglong2 xbn  = *(const ulonglong2*)(smem + OFF_B0NX + j0);
            float o[8];
            #pragma unroll
            for (int q = 0; q < 2; ++q) {
                ull x0p = *(const ull*)(x0d + 4 * bg + 2 * q);
                ull x1p = *(const ull*)(x1d + 4 * bg + 2 * q);
                #pragma unroll
                for (int p2 = 0; p2 < 2; ++p2) {
                    ull w0r = p2 ? xw0r.y : xw0r.x, w1r = p2 ? xw1r.y : xw1r.x;
                    ull w0z = p2 ? xw0z.y : xw0z.x, w1z = p2 ? xw1z.y : xw1z.x;
                    ull w0n = p2 ? xw0n.y : xw0n.x, w1n = p2 ? xw1n.y : xw1n.x;
                    ull bn  = p2 ? xbn.y  : xbn.x;
                    int ai = p2 * 2 + q;
                    ull pr = ffma2(x1p, w1r, ffma2(x0p, w0r, ar[ai]));
                    ull pz = ffma2(x1p, w1z, ffma2(x0p, w0z, az[ai]));
                    ull px = ffma2(x1p, w1n, ffma2(x0p, w0n, bn));
                    float rl, rh, zl, zh, xl, xh, hl, hh;
                    unpk(pr, rl, rh); unpk(pz, zl, zh);
                    unpk(px, xl, xh); unpk(an[ai], hl, hh);
                    float sr_l = fmaf(tanhx(rl), 0.5f, 0.5f);
                    float sr_h = fmaf(tanhx(rh), 0.5f, 0.5f);
                    float sz_l = fmaf(tanhx(zl), 0.5f, 0.5f);
                    float sz_h = fmaf(tanhx(zh), 0.5f, 0.5f);
                    float nl = tanhx(fmaf(sr_l, hl, xl));
                    float nh = tanhx(fmaf(sr_h, hh, xh));
                    int i0 = (2 * p2) * 2 + q, i1 = (2 * p2 + 1) * 2 + q;
                    float e0 = fmaf(sz_l, hp0[i0] - nl, nl);
                    float e1 = fmaf(sz_h, hp0[i1] - nh, nh);
                    o[i0] = e0; o[i1] = e1; hp0[i0] = e0; hp0[i1] = e1;
                }
            }
            #pragma unroll
            for (int jj = 0; jj < 4; ++jj) {
                ulonglong2 st;
                st.x = dup2(o[jj * 2 + 0]);
                st.y = dup2(o[jj * 2 + 1]);
                *(ulonglong2*)(h0w + (j0 + jj) * 64 + hoff) = st;
            }
        }
        __syncthreads();

        // ============ phase 2: GEMM2 (h0new@Wih1 + h1@Whh1) + gates L1 ============
        float2 xv = make_float2(0.0f, 0.0f);
        if (tid < TILE_B && t + 1 < TSTEPS)
            xv = *(const float2*)(x + ((size_t)(t + 1) * BATCH + b0 + tid) * 2);

        ulonglong2 s1r = *(const ulonglong2*)(smem + OFF_MB1 + j0);
        ulonglong2 s1z = *(const ulonglong2*)(smem + OFF_MB1 + 64 + j0);
        ulonglong2 snA = *(const ulonglong2*)(smem + OFF_B1NA + j0);
        ulonglong2 snB = *(const ulonglong2*)(smem + OFF_B1NB + j0);
        ull cr[4], cz[4], cA[4], cB[4];
        cr[0] = s1r.x; cr[1] = s1r.x; cr[2] = s1r.y; cr[3] = s1r.y;
        cz[0] = s1z.x; cz[1] = s1z.x; cz[2] = s1z.y; cz[3] = s1z.y;
        cA[0] = snA.x; cA[1] = snA.x; cA[2] = snA.y; cA[3] = snA.y;
        cB[0] = snB.x; cB[1] = snB.x; cB[2] = snB.y; cB[3] = snB.y;

        #pragma unroll 4
        for (int k = 0; k < HID; ++k) {
            ulonglong2 hA = *(const ulonglong2*)(h0w + k * 64 + hoff);
            ulonglong2 hB = *(const ulonglong2*)(h1r + k * 64 + hoff);
            const float* wa = was + k * GATES + j0;
            const float* wb = wbs + k * GATES + j0;
            ulonglong2 war = *(const ulonglong2*)(wa);
            ulonglong2 waz = *(const ulonglong2*)(wa + 64);
            ulonglong2 wan = *(const ulonglong2*)(wa + 128);
            ulonglong2 wbr = *(const ulonglong2*)(wb);
            ulonglong2 wbz = *(const ulonglong2*)(wb + 64);
            ulonglong2 wbn = *(const ulonglong2*)(wb + 128);
            cr[0] = ffma2(war.x, hA.x, cr[0]); cr[1] = ffma2(war.x, hA.y, cr[1]);
            cr[2] = ffma2(war.y, hA.x, cr[2]); cr[3] = ffma2(war.y, hA.y, cr[3]);
            cz[0] = ffma2(waz.x, hA.x, cz[0]); cz[1] = ffma2(waz.x, hA.y, cz[1]);
            cz[2] = ffma2(waz.y, hA.x, cz[2]); cz[3] = ffma2(waz.y, hA.y, cz[3]);
            cA[0] = ffma2(wan.x, hA.x, cA[0]); cA[1] = ffma2(wan.x, hA.y, cA[1]);
            cA[2] = ffma2(wan.y, hA.x, cA[2]); cA[3] = ffma2(wan.y, hA.y, cA[3]);
            cr[0] = ffma2(wbr.x, hB.x, cr[0]); cr[1] = ffma2(wbr.x, hB.y, cr[1]);
            cr[2] = ffma2(wbr.y, hB.x, cr[2]); cr[3] = ffma2(wbr.y, hB.y, cr[3]);
            cz[0] = ffma2(wbz.x, hB.x, cz[0]); cz[1] = ffma2(wbz.x, hB.y, cz[1]);
            cz[2] = ffma2(wbz.y, hB.x, cz[2]); cz[3] = ffma2(wbz.y, hB.y, cz[3]);
            cB[0] = ffma2(wbn.x, hB.x, cB[0]); cB[1] = ffma2(wbn.x, hB.y, cB[1]);
            cB[2] = ffma2(wbn.y, hB.x, cB[2]); cB[3] = ffma2(wbn.y, hB.y, cB[3]);
        }

        // stage x for step t+1 (global load issued before k-loop)
        if (tid < TILE_B) {
            *(ull*)(x0d + 2 * tid) = dup2(xv.x);
            *(ull*)(x1d + 2 * tid) = dup2(xv.y);
        }

        // epilogue L1
        {
            float o[8];
            #pragma unroll
            for (int q = 0; q < 2; ++q) {
                #pragma unroll
                for (int p2 = 0; p2 < 2; ++p2) {
                    int ai = p2 * 2 + q;
                    float rl, rh, zl, zh, xl, xh, hl, hh;
                    unpk(cr[ai], rl, rh); unpk(cz[ai], zl, zh);
                    unpk(cA[ai], xl, xh); unpk(cB[ai], hl, hh);
                    float sr_l = fmaf(tanhx(rl), 0.5f, 0.5f);
                    float sr_h = fmaf(tanhx(rh), 0.5f, 0.5f);
                    float sz_l = fmaf(tanhx(zl), 0.5f, 0.5f);
                    float sz_h = fmaf(tanhx(zh), 0.5f, 0.5f);
                    float nl = tanhx(fmaf(sr_l, hl, xl));
                    float nh = tanhx(fmaf(sr_h, hh, xh));
                    int i0 = (2 * p2) * 2 + q, i1 = (2 * p2 + 1) * 2 + q;
                    float e0 = fmaf(sz_l, hp1[i0] - nl, nl);
                    float e1 = fmaf(sz_h, hp1[i1] - nh, nh);
                    o[i0] = e0; o[i1] = e1; hp1[i0] = e0; hp1[i1] = e1;
                }
            }
            #pragma unroll
            for (int jj = 0; jj < 4; ++jj) {
                ulonglong2 st;
                st.x = dup2(o[jj * 2 + 0]);
                st.y = dup2(o[jj * 2 + 1]);
                *(ulonglong2*)(h1w + (j0 + jj) * 64 + hoff) = st;
            }
        }
        __syncthreads();
    }

    // ---- final projection (final states in buffer 0: TSTEPS even) ----
    if (tid < TILE_B) {
        int pos = (tid >> 1) * 4 + (tid & 1) * 2;
        const float* wps = smem + OFF_WP;
        float s = bp[0];
        #pragma unroll 8
        for (int k = 0; k < HID; ++k) s = fmaf(h0bs[k * 64 + pos], wps[k], s);
        #pragma unroll 8
        for (int k = 0; k < HID; ++k) s = fmaf(h1bs[k * 64 + pos], wps[HID + k], s);
        out[b0 + tid] = s;
    }
}

extern "C" void kernel_launch(void* const* d_in, const int* in_sizes, int n_in,
                              void* d_out, int out_size) {
    const float* x    = (const float*)d_in[0];
    const float* Wih0 = (const float*)d_in[1];
    const float* Whh0 = (const float*)d_in[2];
    const float* bih0 = (const float*)d_in[3];
    const float* bhh0 = (const float*)d_in[4];
    const float* Wih1 = (const float*)d_in[5];
    const float* Whh1 = (const float*)d_in[6];
    const float* bih1 = (const float*)d_in[7];
    const float* bhh1 = (const float*)d_in[8];
    const float* Wp   = (const float*)d_in[9];
    const float* bp   = (const float*)d_in[10];
    float* out = (float*)d_out;

    cudaFuncSetAttribute(gru2_r4_kernel,
                         cudaFuncAttributeMaxDynamicSharedMemorySize, SMEM_BYTES);
    gru2_r4_kernel<<<NCTA, NTHREADS, SMEM_BYTES>>>(
        x, Wih0, Whh0, bih0, bhh0, Wih1, Whh1, bih1, bhh1, Wp, bp, out);
}